// round 13
// baseline (speedup 1.0000x reference)
#include <cuda_runtime.h>
#include <cuda_bf16.h>
#include <cstdint>
#include <math.h>

#define NB 8192
#define NP 64
#define NK 8
#define ND 512
#define NL 4
#define LN_EPS 1e-5f

__constant__ int c_C[NL]   = {256, 512, 1024, 2048};
__constant__ int c_off[NL] = {0, 256, 768, 1792};

// ---- scratch ----
__device__ float g_pm[NL * 2048];
__device__ float g_spp[NL * 8 * 2];
__device__ float g_spqp[NL * 2];
__device__ float g_u[NL * ND];
__device__ float g_v[NL * ND];
__device__ float g_w[NL * ND];
__device__ float g_up[NL * 32 * ND];
__device__ float g_vp[NL * 32 * ND];
__device__ float g_wp[NL * 32 * ND];
__device__ float g_text[NK * ND];
__device__ __nv_bfloat16 g_Wgb[3840 * ND];          // g_top ⊙ W_top (bf16, stacked)
__device__ __nv_bfloat16 g_Abf[(size_t)NB * 3840];  // pooled bf16, stacked
__device__ float g_rs[NL * NB * 2];
__device__ float g_part[(size_t)NL * 2 * NB * 9];

struct PtrSet {
    const float* pooled[NL];
    const float* proto[NL];
    const float* lng[NL];
    const float* lnb[NL];
    const float* W[NL];
    const float* blin[NL];
    const float* text;
    const float* scale;
};

// ==== L0: mega-prep: rowstats | proto means | text ===========================
#define P0_RS 4096
#define P0_PM 4128
#define P0_TX 4136

__global__ void __launch_bounds__(256) k_prep0(PtrSet ps) {
    int blk = blockIdx.x;
    if (blk < P0_RS) {
        // ---- rowstats + bf16 convert ----
        int gw = (blk * 256 + threadIdx.x) >> 5;
        int lane = threadIdx.x & 31;
        int lvl = gw >> 13;
        int r = gw & (NB - 1);
        int C = c_C[lvl];
        const float4* __restrict__ row = (const float4*)(ps.pooled[lvl] + (size_t)r * C);
        __nv_bfloat162* __restrict__ arow =
            (__nv_bfloat162*)(g_Abf + (size_t)NB * c_off[lvl] + (size_t)r * C);
        int n4 = C >> 2;
        float S = 0.f, Q = 0.f;
        for (int j = lane; j < n4; j += 32) {
            float4 v = row[j];
            S += v.x + v.y + v.z + v.w;
            Q += v.x * v.x + v.y * v.y + v.z * v.z + v.w * v.w;
            arow[j * 2]     = __floats2bfloat162_rn(v.x, v.y);
            arow[j * 2 + 1] = __floats2bfloat162_rn(v.z, v.w);
        }
        #pragma unroll
        for (int o = 16; o; o >>= 1) {
            S += __shfl_xor_sync(0xffffffffu, S, o);
            Q += __shfl_xor_sync(0xffffffffu, Q, o);
        }
        if (lane == 0) { g_rs[gw * 2] = S; g_rs[gw * 2 + 1] = Q; }
    } else if (blk < P0_PM) {
        // ---- proto column means + spqp partials ----
        int q = blk - P0_RS;
        int lvl = q >> 3, bx = q & 7;
        int C = c_C[lvl];
        int seg = C / 8;
        int j0 = bx * seg;
        const float* __restrict__ proto = ps.proto[lvl];
        float sS = 0.f, sQ = 0.f;
        for (int j = j0 + threadIdx.x; j < j0 + seg; j += 256) {
            float s = 0.f;
            #pragma unroll 8
            for (int p = 0; p < NP; ++p) s += proto[p * C + j];
            float m = s * (1.0f / NP);
            g_pm[lvl * 2048 + j] = m;
            sS += m; sQ += m * m;
        }
        __shared__ float r1[256], r2[256];
        int t = threadIdx.x;
        r1[t] = sS; r2[t] = sQ;
        __syncthreads();
        for (int o = 128; o > 0; o >>= 1) {
            if (t < o) { r1[t] += r1[t + o]; r2[t] += r2[t + o]; }
            __syncthreads();
        }
        if (t == 0) { g_spp[q * 2] = r1[0]; g_spp[q * 2 + 1] = r2[0]; }
    } else {
        // ---- text normalize ----
        int k = blk - P0_PM;
        int d = threadIdx.x;
        float x0 = ps.text[k * ND + d];
        float x1 = ps.text[k * ND + 256 + d];
        __shared__ float red[256];
        red[d] = x0 * x0 + x1 * x1;
        __syncthreads();
        for (int o = 128; o > 0; o >>= 1) {
            if (d < o) red[d] += red[d + o];
            __syncthreads();
        }
        float n = fmaxf(sqrtf(red[0]), 1e-12f);
        float sc = fmaxf(ps.scale[0], 1e-4f) * (1.0f / sqrtf((float)ND));
        g_text[k * ND + d]       = x0 / n * sc;
        g_text[k * ND + 256 + d] = x1 / n * sc;
    }
}

// ==== L1: u,v,w partials + Wgb store (single W pass, 128 blocks) =============
__global__ void __launch_bounds__(512) k_uvw(PtrSet ps) {
    int lvl = blockIdx.y;
    int bx = blockIdx.x;                 // 0..31
    int C = c_C[lvl];
    int seg = (2 * C) / 32;
    int j0 = bx * seg;
    int d = threadIdx.x;                 // 512
    const float* __restrict__ W  = ps.W[lvl];
    const float* __restrict__ gg = ps.lng[lvl];
    const float* __restrict__ bb = ps.lnb[lvl];
    const float* __restrict__ pm = g_pm + lvl * 2048;
    __nv_bfloat16* __restrict__ Wgb = g_Wgb + (size_t)c_off[lvl] * ND;
    float u = 0.f, v = 0.f, w = 0.f;
    for (int j = j0; j < j0 + seg; ++j) {
        float Wv = W[(size_t)j * ND + d];
        float gv = gg[j];
        float gw = gv * Wv;
        v += gw;
        w += bb[j] * Wv;
        if (j >= C) u += pm[j - C] * gw;
        else        Wgb[(size_t)j * ND + d] = __float2bfloat16(gw);
    }
    int o = (lvl * 32 + bx) * ND + d;
    g_up[o] = u; g_vp[o] = v; g_wp[o] = w;
}

// ==== L2: reduce partials + bias + combine spqp ==============================
__global__ void k_uvw_fin(PtrSet ps) {
    int lvl = blockIdx.x, d = threadIdx.x;
    float u = 0.f, v = 0.f, w = 0.f;
    #pragma unroll
    for (int p = 0; p < 32; ++p) {
        int o = (lvl * 32 + p) * ND + d;
        u += g_up[o]; v += g_vp[o]; w += g_wp[o];
    }
    g_u[lvl * ND + d] = u;
    g_v[lvl * ND + d] = v;
    g_w[lvl * ND + d] = w + ps.blin[lvl][d];
    if (d == 0) {
        float s = 0.f, q = 0.f;
        #pragma unroll
        for (int p = 0; p < 8; ++p) {
            s += g_spp[(lvl * 8 + p) * 2];
            q += g_spp[(lvl * 8 + p) * 2 + 1];
        }
        g_spqp[lvl * 2] = s; g_spqp[lvl * 2 + 1] = q;
    }
}

// ===== L3: fused GEMM (bf16 mma.sync) + LN/ReLU + partial l2norm/dots ========
// BM=128, BN=256, BK=64 stages, FOUR smem stages, cross-iteration fragment
// prefetch: commits run one stage ahead so stage it+1 is barrier-visible
// during iter it; the MMA stream never waits on a cold ldmatrix.
// smem layout (bytes):
//   [0)      Bs: 4 x 64 x 264 bf16 = 135168   (stage0 reused as red[] f32)
//   [135168) As: 4 x 128 x 72 bf16 = 73728
//   [208896) text: 8 x 256 f32     = 8192
//   [217088) uvw:  3 x 256 f32     = 3072
#define SM_AS   135168
#define SM_TEXT 208896
#define SM_UVW  217088
#define SM_TOT  220160
#define ASTRIDE 72
#define BSTRIDE 264
#define BNH 256
#define A_STAGE (128 * ASTRIDE * 2)
#define B_STAGE (64 * BSTRIDE * 2)

__device__ __forceinline__ void cp16(uint32_t dst, const void* src) {
    asm volatile("cp.async.cg.shared.global [%0], [%1], 16;\n" :: "r"(dst), "l"(src));
}

// load A(2 x ldmatrix.x4) + B(4 x ldmatrix.x4.trans) frags for (Ab,Bb,ks) -> buffer pb
#define LOAD_FRAGS(Abase, Bbase, ks, pb)                                          \
    do {                                                                          \
        _Pragma("unroll")                                                         \
        for (int mf = 0; mf < 2; ++mf) {                                          \
            uint32_t addr = (Abase) + ((wm * 32 + mf * 16 + (lane & 15)) * ASTRIDE\
                                  + (ks) + (lane >> 4) * 8) * 2;                  \
            asm volatile("ldmatrix.sync.aligned.m8n8.x4.shared.b16 "              \
                         "{%0,%1,%2,%3}, [%4];\n"                                 \
                         : "=r"(af[pb][mf][0]), "=r"(af[pb][mf][1]),              \
                           "=r"(af[pb][mf][2]), "=r"(af[pb][mf][3])               \
                         : "r"(addr));                                            \
        }                                                                         \
        _Pragma("unroll")                                                         \
        for (int p = 0; p < 4; ++p) {                                             \
            uint32_t addr = (Bbase) + (((ks) + (lane & 15)) * BSTRIDE             \
                                  + wn * 64 + p * 16 + (lane >> 4) * 8) * 2;      \
            asm volatile("ldmatrix.sync.aligned.m8n8.x4.trans.shared.b16 "        \
                         "{%0,%1,%2,%3}, [%4];\n"                                 \
                         : "=r"(bfr[pb][2 * p][0]), "=r"(bfr[pb][2 * p][1]),      \
                           "=r"(bfr[pb][2 * p + 1][0]),                           \
                           "=r"(bfr[pb][2 * p + 1][1])                            \
                         : "r"(addr));                                            \
        }                                                                         \
    } while (0)

__global__ void __launch_bounds__(512, 1) k_fused() {
    extern __shared__ char smem[];
    const int lvl = 3 - blockIdx.z;      // heavy levels first
    const int half = blockIdx.y;
    const int C = c_C[lvl];
    const int bm = blockIdx.x * 128;
    const int tid = threadIdx.x;
    const int wid = tid >> 5, lane = tid & 31;
    const int wm = wid >> 2, wn = wid & 3;

    const __nv_bfloat16* __restrict__ Ag = g_Abf + (size_t)NB * c_off[lvl] + (size_t)bm * C;
    const __nv_bfloat16* __restrict__ Bg = g_Wgb + (size_t)c_off[lvl] * ND + half * BNH;

    float* text_s = (float*)(smem + SM_TEXT);
    float* uvw_s  = (float*)(smem + SM_UVW);
    float* red_s  = (float*)smem;

    const uint32_t Bs_u = (uint32_t)__cvta_generic_to_shared(smem);
    const uint32_t As_u = (uint32_t)__cvta_generic_to_shared(smem + SM_AS);

    for (int i = tid; i < NK * BNH; i += 512) {
        int k = i >> 8, c = i & (BNH - 1);
        text_s[i] = g_text[k * ND + half * BNH + c];
    }
    if (tid < BNH) {
        uvw_s[tid]           = g_u[lvl * ND + half * BNH + tid];
        uvw_s[BNH + tid]     = g_v[lvl * ND + half * BNH + tid];
        uvw_s[2 * BNH + tid] = g_w[lvl * ND + half * BNH + tid];
    }

    float acc[2][8][4];
    #pragma unroll
    for (int i = 0; i < 2; ++i)
        #pragma unroll
        for (int j = 0; j < 8; ++j)
            #pragma unroll
            for (int r = 0; r < 4; ++r) acc[i][j][r] = 0.f;

    const int niter = C >> 6;            // BK=64, niter >= 4

    auto load_stage = [&](int it) {
        int buf = it & 3;
        int k0 = it << 6;
        #pragma unroll
        for (int i = 0; i < 2; ++i) {
            int idx = tid + i * 512;
            int r = idx >> 3, c = idx & 7;
            cp16(As_u + buf * A_STAGE + (r * ASTRIDE + c * 8) * 2,
                 Ag + (size_t)r * C + k0 + c * 8);
        }
        #pragma unroll
        for (int i = 0; i < 4; ++i) {
            int idx = tid + i * 512;
            int r = idx >> 5, c = idx & 31;
            cp16(Bs_u + buf * B_STAGE + (r * BSTRIDE + c * 8) * 2,
                 Bg + (size_t)(k0 + r) * ND + c * 8);
        }
        asm volatile("cp.async.commit_group;\n" ::: "memory");
    };

    // preamble: 3 stages in flight; stage 0 visible
    load_stage(0);
    load_stage(1);
    load_stage(2);
    asm volatile("cp.async.wait_group 2;\n" ::: "memory");
    __syncthreads();

    uint32_t af[2][2][4];
    uint32_t bfr[2][8][2];
    LOAD_FRAGS(As_u, Bs_u, 0, 0);        // iter0, stage0, ks=0
    int pb = 0;

    for (int it = 0; it < niter; ++it) {
        // stage it+1 completion BEFORE the barrier -> cross-thread visible after it
        if (it + 2 < niter)
            asm volatile("cp.async.wait_group 1;\n" ::: "memory");
        else
            asm volatile("cp.async.wait_group 0;\n" ::: "memory");
        __syncthreads();
        if (it + 3 < niter) load_stage(it + 3);

        const uint32_t Ab  = As_u + (it & 3) * A_STAGE;
        const uint32_t Bb  = Bs_u + (it & 3) * B_STAGE;
        const uint32_t Ab1 = As_u + ((it + 1) & 3) * A_STAGE;
        const uint32_t Bb1 = Bs_u + ((it + 1) & 3) * B_STAGE;

        #pragma unroll
        for (int ks4 = 0; ks4 < 4; ++ks4) {
            const int cur = pb;
            const int nxt = pb ^ 1;
            if (ks4 < 3) {
                LOAD_FRAGS(Ab, Bb, (ks4 + 1) * 16, nxt);
            } else if (it + 1 < niter) {
                LOAD_FRAGS(Ab1, Bb1, 0, nxt);   // cross-iteration prefetch
            }
            #pragma unroll
            for (int mf = 0; mf < 2; ++mf)
                #pragma unroll
                for (int nf = 0; nf < 8; ++nf)
                    asm volatile(
                        "mma.sync.aligned.m16n8k16.row.col.f32.bf16.bf16.f32 "
                        "{%0,%1,%2,%3}, {%4,%5,%6,%7}, {%8,%9}, {%0,%1,%2,%3};\n"
                        : "+f"(acc[mf][nf][0]), "+f"(acc[mf][nf][1]),
                          "+f"(acc[mf][nf][2]), "+f"(acc[mf][nf][3])
                        : "r"(af[cur][mf][0]), "r"(af[cur][mf][1]),
                          "r"(af[cur][mf][2]), "r"(af[cur][mf][3]),
                          "r"(bfr[cur][nf][0]), "r"(bfr[cur][nf][1]));
            pb ^= 1;
        }
    }

    // ---- epilogue: LN + ReLU, partial sq + 8 text dots per row ----
    const float Sp = g_spqp[lvl * 2], Qp = g_spqp[lvl * 2 + 1];
    const float inv2C = 1.0f / (2.0f * (float)C);
    const int qr = lane >> 2, qc = (lane & 3) * 2;

    float osq[2][2];
    float od[2][2][NK];
    #pragma unroll
    for (int mf = 0; mf < 2; ++mf) {
        int R0 = wm * 32 + mf * 16 + qr;
        float2 sqr0 = ((const float2*)g_rs)[lvl * NB + bm + R0];
        float2 sqr1 = ((const float2*)g_rs)[lvl * NB + bm + R0 + 8];
        float mean0 = (sqr0.x + Sp) * inv2C;
        float var0  = (sqr0.y + Qp) * inv2C - mean0 * mean0;
        float s0 = rsqrtf(var0 + LN_EPS), sm0 = s0 * mean0;
        float mean1 = (sqr1.x + Sp) * inv2C;
        float var1  = (sqr1.y + Qp) * inv2C - mean1 * mean1;
        float s1 = rsqrtf(var1 + LN_EPS), sm1 = s1 * mean1;

        float sq0 = 0.f, sq1 = 0.f;
        float d0[NK], d1[NK];
        #pragma unroll
        for (int k = 0; k < NK; ++k) { d0[k] = 0.f; d1[k] = 0.f; }

        #pragma unroll
        for (int nf = 0; nf < 8; ++nf) {
            #pragma unroll
            for (int r = 0; r < 4; ++r) {
                int col = wn * 64 + nf * 8 + qc + (r & 1);
                float s  = (r < 2) ? s0  : s1;
                float sm = (r < 2) ? sm0 : sm1;
                float hv = s * (acc[mf][nf][r] + uvw_s[col]) - sm * uvw_s[BNH + col]
                           + uvw_s[2 * BNH + col];
                hv = fmaxf(hv, 0.f);
                if (r < 2) {
                    sq0 += hv * hv;
                    #pragma unroll
                    for (int k = 0; k < NK; ++k) d0[k] += hv * text_s[k * BNH + col];
                } else {
                    sq1 += hv * hv;
                    #pragma unroll
                    for (int k = 0; k < NK; ++k) d1[k] += hv * text_s[k * BNH + col];
                }
            }
        }
        #pragma unroll
        for (int o = 1; o <= 2; o <<= 1) {
            sq0 += __shfl_xor_sync(0xffffffffu, sq0, o);
            sq1 += __shfl_xor_sync(0xffffffffu, sq1, o);
            #pragma unroll
            for (int k = 0; k < NK; ++k) {
                d0[k] += __shfl_xor_sync(0xffffffffu, d0[k], o);
                d1[k] += __shfl_xor_sync(0xffffffffu, d1[k], o);
            }
        }
        osq[mf][0] = sq0; osq[mf][1] = sq1;
        #pragma unroll
        for (int k = 0; k < NK; ++k) { od[mf][0][k] = d0[k]; od[mf][1][k] = d1[k]; }
    }
    __syncthreads();           // all mainloop smem reads done -> red_s overlay safe

    if ((lane & 3) == 0) {
        #pragma unroll
        for (int mf = 0; mf < 2; ++mf) {
            int R0 = wm * 32 + mf * 16 + qr;
            #pragma unroll
            for (int k = 0; k < NK; ++k) {
                red_s[(wn * 128 + R0) * 9 + k]     = od[mf][0][k];
                red_s[(wn * 128 + R0 + 8) * 9 + k] = od[mf][1][k];
            }
            red_s[(wn * 128 + R0) * 9 + 8]     = osq[mf][0];
            red_s[(wn * 128 + R0 + 8) * 9 + 8] = osq[mf][1];
        }
    }
    __syncthreads();

    for (int idx = tid; idx < 128 * 9; idx += 512) {
        int row = idx / 9, kk = idx - row * 9;
        float s = red_s[(0 * 128 + row) * 9 + kk] + red_s[(1 * 128 + row) * 9 + kk]
                + red_s[(2 * 128 + row) * 9 + kk] + red_s[(3 * 128 + row) * 9 + kk];
        g_part[((size_t)(lvl * 2 + half) * NB + bm + row) * 9 + kk] = s;
    }
}

// ==== L4: combine halves, normalize, softmax over L=4 ========================
__global__ void k_final(float* __restrict__ out) {
    int id = blockIdx.x * blockDim.x + threadIdx.x;
    if (id >= NB * NK) return;
    int b = id >> 3, k = id & 7;
    float lg[NL];
    #pragma unroll
    for (int lvl = 0; lvl < NL; ++lvl) {
        const float* p0 = &g_part[((size_t)(lvl * 2 + 0) * NB + b) * 9];
        const float* p1 = &g_part[((size_t)(lvl * 2 + 1) * NB + b) * 9];
        float dq = p0[k] + p1[k];
        float sq = p0[8] + p1[8];
        lg[lvl] = dq / fmaxf(sqrtf(sq), 1e-12f);
    }
    float mx = fmaxf(fmaxf(lg[0], lg[1]), fmaxf(lg[2], lg[3]));
    float e0 = expf(lg[0] - mx), e1 = expf(lg[1] - mx);
    float e2 = expf(lg[2] - mx), e3 = expf(lg[3] - mx);
    float inv = 1.0f / (e0 + e1 + e2 + e3);
    ((float4*)out)[(size_t)b * NK + k] = make_float4(e0 * inv, e1 * inv, e2 * inv, e3 * inv);
}

extern "C" void kernel_launch(void* const* d_in, const int* in_sizes, int n_in,
                              void* d_out, int out_size) {
    PtrSet ps;
    bool interleaved = (in_sizes[1] == NP * 256);
    if (interleaved) {
        for (int i = 0; i < NL; ++i) {
            ps.pooled[i] = (const float*)d_in[6 * i + 0];
            ps.proto[i]  = (const float*)d_in[6 * i + 1];
            ps.lng[i]    = (const float*)d_in[6 * i + 2];
            ps.lnb[i]    = (const float*)d_in[6 * i + 3];
            ps.W[i]      = (const float*)d_in[6 * i + 4];
            ps.blin[i]   = (const float*)d_in[6 * i + 5];
        }
    } else {
        for (int i = 0; i < NL; ++i) {
            ps.pooled[i] = (const float*)d_in[0 + i];
            ps.proto[i]  = (const float*)d_in[4 + i];
            ps.lng[i]    = (const float*)d_in[8 + i];
            ps.lnb[i]    = (const float*)d_in[12 + i];
            ps.W[i]      = (const float*)d_in[16 + i];
            ps.blin[i]   = (const float*)d_in[20 + i];
        }
    }
    ps.text  = (const float*)d_in[24];
    ps.scale = (const float*)d_in[25];
    float* out = (float*)d_out;

    static bool attr_done = false;
    if (!attr_done) {
        cudaFuncSetAttribute(k_fused, cudaFuncAttributeMaxDynamicSharedMemorySize, SM_TOT);
        attr_done = true;
    }

    k_prep0<<<P0_TX, 256>>>(ps);                        // 0
    k_uvw<<<dim3(32, NL), ND>>>(ps);                    // 1
    k_uvw_fin<<<NL, ND>>>(ps);                          // 2
    k_fused<<<dim3(64, 2, NL), 512, SM_TOT>>>();        // 3 (ncu target)
    k_final<<<(NB * NK + 255) / 256, 256>>>(out);       // 4
}

// round 14
// speedup vs baseline: 1.2409x; 1.2409x over previous
#include <cuda_runtime.h>
#include <cuda_bf16.h>
#include <cstdint>
#include <math.h>

#define NB 8192
#define NP 64
#define NK 8
#define ND 512
#define NL 4
#define LN_EPS 1e-5f

__constant__ int c_C[NL]   = {256, 512, 1024, 2048};
__constant__ int c_off[NL] = {0, 256, 768, 1792};

// ---- scratch ----
__device__ float g_pm[NL * 2048];
__device__ float g_spp[NL * 8 * 2];
__device__ float g_spqp[NL * 2];
__device__ float g_u[NL * ND];
__device__ float g_v[NL * ND];
__device__ float g_w[NL * ND];
__device__ float g_up[NL * 64 * ND];
__device__ float g_vp[NL * 64 * ND];
__device__ float g_wp[NL * 64 * ND];
__device__ float g_text[NK * ND];
__device__ __nv_bfloat16 g_Wgb[3840 * ND];          // g_top ⊙ W_top (bf16, stacked)
__device__ __nv_bfloat16 g_Abf[(size_t)NB * 3840];  // pooled bf16, stacked
__device__ float g_rs[NL * NB * 2];
__device__ float g_part[(size_t)NL * 2 * NB * 9];

struct PtrSet {
    const float* pooled[NL];
    const float* proto[NL];
    const float* lng[NL];
    const float* lnb[NL];
    const float* W[NL];
    const float* blin[NL];
    const float* text;
    const float* scale;
};

// ==== L0: mega-prep: rowstats | proto means | text | Wg ======================
#define P0_RS 4096
#define P0_PM 4128
#define P0_TX 4136
#define P0_WG 11816   // + 7680 blocks for Wg

__global__ void __launch_bounds__(256) k_prep0(PtrSet ps) {
    int blk = blockIdx.x;
    if (blk < P0_RS) {
        // ---- rowstats + bf16 convert ----
        int gw = (blk * 256 + threadIdx.x) >> 5;
        int lane = threadIdx.x & 31;
        int lvl = gw >> 13;
        int r = gw & (NB - 1);
        int C = c_C[lvl];
        const float4* __restrict__ row = (const float4*)(ps.pooled[lvl] + (size_t)r * C);
        __nv_bfloat162* __restrict__ arow =
            (__nv_bfloat162*)(g_Abf + (size_t)NB * c_off[lvl] + (size_t)r * C);
        int n4 = C >> 2;
        float S = 0.f, Q = 0.f;
        for (int j = lane; j < n4; j += 32) {
            float4 v = row[j];
            S += v.x + v.y + v.z + v.w;
            Q += v.x * v.x + v.y * v.y + v.z * v.z + v.w * v.w;
            arow[j * 2]     = __floats2bfloat162_rn(v.x, v.y);
            arow[j * 2 + 1] = __floats2bfloat162_rn(v.z, v.w);
        }
        #pragma unroll
        for (int o = 16; o; o >>= 1) {
            S += __shfl_xor_sync(0xffffffffu, S, o);
            Q += __shfl_xor_sync(0xffffffffu, Q, o);
        }
        if (lane == 0) { g_rs[gw * 2] = S; g_rs[gw * 2 + 1] = Q; }
    } else if (blk < P0_PM) {
        // ---- proto column means + spqp partials ----
        int q = blk - P0_RS;
        int lvl = q >> 3, bx = q & 7;
        int C = c_C[lvl];
        int seg = C / 8;
        int j0 = bx * seg;
        const float* __restrict__ proto = ps.proto[lvl];
        float sS = 0.f, sQ = 0.f;
        for (int j = j0 + threadIdx.x; j < j0 + seg; j += 256) {
            float s = 0.f;
            #pragma unroll 8
            for (int p = 0; p < NP; ++p) s += proto[p * C + j];
            float m = s * (1.0f / NP);
            g_pm[lvl * 2048 + j] = m;
            sS += m; sQ += m * m;
        }
        __shared__ float r1[256], r2[256];
        int t = threadIdx.x;
        r1[t] = sS; r2[t] = sQ;
        __syncthreads();
        for (int o = 128; o > 0; o >>= 1) {
            if (t < o) { r1[t] += r1[t + o]; r2[t] += r2[t + o]; }
            __syncthreads();
        }
        if (t == 0) { g_spp[q * 2] = r1[0]; g_spp[q * 2 + 1] = r2[0]; }
    } else if (blk < P0_TX) {
        // ---- text normalize ----
        int k = blk - P0_PM;
        int d = threadIdx.x;
        float x0 = ps.text[k * ND + d];
        float x1 = ps.text[k * ND + 256 + d];
        __shared__ float red[256];
        red[d] = x0 * x0 + x1 * x1;
        __syncthreads();
        for (int o = 128; o > 0; o >>= 1) {
            if (d < o) red[d] += red[d + o];
            __syncthreads();
        }
        float n = fmaxf(sqrtf(red[0]), 1e-12f);
        float sc = fmaxf(ps.scale[0], 1e-4f) * (1.0f / sqrtf((float)ND));
        g_text[k * ND + d]       = x0 / n * sc;
        g_text[k * ND + 256 + d] = x1 / n * sc;
    } else {
        // ---- Wg = g_top ⊙ W_top (bf16) ----
        int idx = (blk - P0_TX) * 256 + threadIdx.x;
        if (idx >= 3840 * ND) return;
        int row = idx / ND, d = idx % ND;
        int lvl, j;
        if (row < 256)       { lvl = 0; j = row; }
        else if (row < 768)  { lvl = 1; j = row - 256; }
        else if (row < 1792) { lvl = 2; j = row - 768; }
        else                 { lvl = 3; j = row - 1792; }
        g_Wgb[idx] = __float2bfloat16(ps.lng[lvl][j] * ps.W[lvl][(size_t)j * ND + d]);
    }
}

// ==== L1: u,v,w partials (256 blocks, unrolled loads) ========================
__global__ void __launch_bounds__(512) k_uvw(PtrSet ps) {
    int lvl = blockIdx.y;
    int bx = blockIdx.x;                 // 0..63
    int C = c_C[lvl];
    int seg = (2 * C) / 64;              // 8..64
    int j0 = bx * seg;
    int d = threadIdx.x;                 // 512
    const float* __restrict__ W  = ps.W[lvl];
    const float* __restrict__ gg = ps.lng[lvl];
    const float* __restrict__ bb = ps.lnb[lvl];
    const float* __restrict__ pm = g_pm + lvl * 2048;
    float u = 0.f, v = 0.f, w = 0.f;
    #pragma unroll 4
    for (int j = j0; j < j0 + seg; ++j) {
        float Wv = W[(size_t)j * ND + d];
        float gv = gg[j];
        v += gv * Wv;
        w += bb[j] * Wv;
        if (j >= C) u += pm[j - C] * gv * Wv;
    }
    int o = (lvl * 64 + bx) * ND + d;
    g_up[o] = u; g_vp[o] = v; g_wp[o] = w;
}

// ==== L2: reduce partials + bias + combine spqp ==============================
__global__ void k_uvw_fin(PtrSet ps) {
    int lvl = blockIdx.x, d = threadIdx.x;
    float u = 0.f, v = 0.f, w = 0.f;
    #pragma unroll 8
    for (int p = 0; p < 64; ++p) {
        int o = (lvl * 64 + p) * ND + d;
        u += g_up[o]; v += g_vp[o]; w += g_wp[o];
    }
    g_u[lvl * ND + d] = u;
    g_v[lvl * ND + d] = v;
    g_w[lvl * ND + d] = w + ps.blin[lvl][d];
    if (d == 0) {
        float s = 0.f, q = 0.f;
        #pragma unroll
        for (int p = 0; p < 8; ++p) {
            s += g_spp[(lvl * 8 + p) * 2];
            q += g_spp[(lvl * 8 + p) * 2 + 1];
        }
        g_spqp[lvl * 2] = s; g_spqp[lvl * 2 + 1] = q;
    }
}

// ===== L3: fused GEMM (bf16 mma.sync) + LN/ReLU + partial l2norm/dots ========
// BM=128, BN=256 (half of D), BK=64 stages. 512 threads = 16 warps (4x4).
// Warp tile 32x64. 3-stage cp.async pipeline, ONE sync/iter, register
// double-buffered fragments (prefetch ks+16 during mma of ks).  [R11 proven]
#define SM_AS   101376
#define SM_TEXT 156672
#define SM_UVW  164864
#define SM_TOT  167936
#define ASTRIDE 72
#define BSTRIDE 264
#define BNH 256
#define A_STAGE (128 * ASTRIDE * 2)
#define B_STAGE (64 * BSTRIDE * 2)

__device__ __forceinline__ void cp16(uint32_t dst, const void* src) {
    asm volatile("cp.async.cg.shared.global [%0], [%1], 16;\n" :: "r"(dst), "l"(src));
}

// load A(2 x ldmatrix.x4) + B(4 x ldmatrix.x4.trans) frags for one ks into buffer pb
#define LOAD_FRAGS(ks, pb)                                                        \
    do {                                                                          \
        _Pragma("unroll")                                                         \
        for (int mf = 0; mf < 2; ++mf) {                                          \
            uint32_t addr = Ab + ((wm * 32 + mf * 16 + (lane & 15)) * ASTRIDE     \
                                  + (ks) + (lane >> 4) * 8) * 2;                  \
            asm volatile("ldmatrix.sync.aligned.m8n8.x4.shared.b16 "              \
                         "{%0,%1,%2,%3}, [%4];\n"                                 \
                         : "=r"(af[pb][mf][0]), "=r"(af[pb][mf][1]),              \
                           "=r"(af[pb][mf][2]), "=r"(af[pb][mf][3])               \
                         : "r"(addr));                                            \
        }                                                                         \
        _Pragma("unroll")                                                         \
        for (int p = 0; p < 4; ++p) {                                             \
            uint32_t addr = Bb + (((ks) + (lane & 15)) * BSTRIDE                  \
                                  + wn * 64 + p * 16 + (lane >> 4) * 8) * 2;      \
            asm volatile("ldmatrix.sync.aligned.m8n8.x4.trans.shared.b16 "        \
                         "{%0,%1,%2,%3}, [%4];\n"                                 \
                         : "=r"(bfr[pb][2 * p][0]), "=r"(bfr[pb][2 * p][1]),      \
                           "=r"(bfr[pb][2 * p + 1][0]),                           \
                           "=r"(bfr[pb][2 * p + 1][1])                            \
                         : "r"(addr));                                            \
        }                                                                         \
    } while (0)

__global__ void __launch_bounds__(512, 1) k_fused() {
    extern __shared__ char smem[];
    const int lvl = 3 - blockIdx.z;      // heavy levels first
    const int half = blockIdx.y;
    const int C = c_C[lvl];
    const int bm = blockIdx.x * 128;
    const int tid = threadIdx.x;
    const int wid = tid >> 5, lane = tid & 31;
    const int wm = wid >> 2, wn = wid & 3;

    const __nv_bfloat16* __restrict__ Ag = g_Abf + (size_t)NB * c_off[lvl] + (size_t)bm * C;
    const __nv_bfloat16* __restrict__ Bg = g_Wgb + (size_t)c_off[lvl] * ND + half * BNH;

    float* text_s = (float*)(smem + SM_TEXT);
    float* uvw_s  = (float*)(smem + SM_UVW);
    float* red_s  = (float*)smem;

    const uint32_t Bs_u = (uint32_t)__cvta_generic_to_shared(smem);
    const uint32_t As_u = (uint32_t)__cvta_generic_to_shared(smem + SM_AS);

    for (int i = tid; i < NK * BNH; i += 512) {
        int k = i >> 8, c = i & (BNH - 1);
        text_s[i] = g_text[k * ND + half * BNH + c];
    }
    if (tid < BNH) {
        uvw_s[tid]           = g_u[lvl * ND + half * BNH + tid];
        uvw_s[BNH + tid]     = g_v[lvl * ND + half * BNH + tid];
        uvw_s[2 * BNH + tid] = g_w[lvl * ND + half * BNH + tid];
    }

    float acc[2][8][4];
    #pragma unroll
    for (int i = 0; i < 2; ++i)
        #pragma unroll
        for (int j = 0; j < 8; ++j)
            #pragma unroll
            for (int r = 0; r < 4; ++r) acc[i][j][r] = 0.f;

    const int niter = C >> 6;            // BK=64

    auto load_stage = [&](int it) {
        int buf = it - (it / 3) * 3;
        int k0 = it << 6;
        #pragma unroll
        for (int i = 0; i < 2; ++i) {
            int idx = tid + i * 512;
            int r = idx >> 3, c = idx & 7;
            cp16(As_u + buf * A_STAGE + (r * ASTRIDE + c * 8) * 2,
                 Ag + (size_t)r * C + k0 + c * 8);
        }
        #pragma unroll
        for (int i = 0; i < 4; ++i) {
            int idx = tid + i * 512;
            int r = idx >> 5, c = idx & 31;
            cp16(Bs_u + buf * B_STAGE + (r * BSTRIDE + c * 8) * 2,
                 Bg + (size_t)(k0 + r) * ND + c * 8);
        }
        asm volatile("cp.async.commit_group;\n" ::: "memory");
    };

    load_stage(0);
    if (niter > 1) load_stage(1);

    for (int it = 0; it < niter; ++it) {
        if (it + 1 < niter)
            asm volatile("cp.async.wait_group 1;\n" ::: "memory");
        else
            asm volatile("cp.async.wait_group 0;\n" ::: "memory");
        __syncthreads();
        // buffer (it+2)%3 == (it-1)%3 was fully consumed before this barrier
        if (it + 2 < niter) load_stage(it + 2);

        const int buf = it - (it / 3) * 3;
        const uint32_t Ab = As_u + buf * A_STAGE;
        const uint32_t Bb = Bs_u + buf * B_STAGE;

        uint32_t af[2][2][4];
        uint32_t bfr[2][8][2];
        LOAD_FRAGS(0, 0);

        #pragma unroll
        for (int ks4 = 0; ks4 < 4; ++ks4) {
            const int cur = ks4 & 1;
            if (ks4 < 3) {
                const int nxt = cur ^ 1;
                LOAD_FRAGS((ks4 + 1) * 16, nxt);
            }
            #pragma unroll
            for (int mf = 0; mf < 2; ++mf)
                #pragma unroll
                for (int nf = 0; nf < 8; ++nf)
                    asm volatile(
                        "mma.sync.aligned.m16n8k16.row.col.f32.bf16.bf16.f32 "
                        "{%0,%1,%2,%3}, {%4,%5,%6,%7}, {%8,%9}, {%0,%1,%2,%3};\n"
                        : "+f"(acc[mf][nf][0]), "+f"(acc[mf][nf][1]),
                          "+f"(acc[mf][nf][2]), "+f"(acc[mf][nf][3])
                        : "r"(af[cur][mf][0]), "r"(af[cur][mf][1]),
                          "r"(af[cur][mf][2]), "r"(af[cur][mf][3]),
                          "r"(bfr[cur][nf][0]), "r"(bfr[cur][nf][1]));
        }
        // no tail sync: next iteration's head barrier provides the ordering
    }

    // ---- epilogue: LN + ReLU, partial sq + 8 text dots per row ----
    const float Sp = g_spqp[lvl * 2], Qp = g_spqp[lvl * 2 + 1];
    const float inv2C = 1.0f / (2.0f * (float)C);
    const int qr = lane >> 2, qc = (lane & 3) * 2;

    float osq[2][2];
    float od[2][2][NK];
    #pragma unroll
    for (int mf = 0; mf < 2; ++mf) {
        int R0 = wm * 32 + mf * 16 + qr;
        float2 sqr0 = ((const float2*)g_rs)[lvl * NB + bm + R0];
        float2 sqr1 = ((const float2*)g_rs)[lvl * NB + bm + R0 + 8];
        float mean0 = (sqr0.x + Sp) * inv2C;
        float var0  = (sqr0.y + Qp) * inv2C - mean0 * mean0;
        float s0 = rsqrtf(var0 + LN_EPS), sm0 = s0 * mean0;
        float mean1 = (sqr1.x + Sp) * inv2C;
        float var1  = (sqr1.y + Qp) * inv2C - mean1 * mean1;
        float s1 = rsqrtf(var1 + LN_EPS), sm1 = s1 * mean1;

        float sq0 = 0.f, sq1 = 0.f;
        float d0[NK], d1[NK];
        #pragma unroll
        for (int k = 0; k < NK; ++k) { d0[k] = 0.f; d1[k] = 0.f; }

        #pragma unroll
        for (int nf = 0; nf < 8; ++nf) {
            #pragma unroll
            for (int r = 0; r < 4; ++r) {
                int col = wn * 64 + nf * 8 + qc + (r & 1);
                float s  = (r < 2) ? s0  : s1;
                float sm = (r < 2) ? sm0 : sm1;
                float hv = s * (acc[mf][nf][r] + uvw_s[col]) - sm * uvw_s[BNH + col]
                           + uvw_s[2 * BNH + col];
                hv = fmaxf(hv, 0.f);
                if (r < 2) {
                    sq0 += hv * hv;
                    #pragma unroll
                    for (int k = 0; k < NK; ++k) d0[k] += hv * text_s[k * BNH + col];
                } else {
                    sq1 += hv * hv;
                    #pragma unroll
                    for (int k = 0; k < NK; ++k) d1[k] += hv * text_s[k * BNH + col];
                }
            }
        }
        #pragma unroll
        for (int o = 1; o <= 2; o <<= 1) {
            sq0 += __shfl_xor_sync(0xffffffffu, sq0, o);
            sq1 += __shfl_xor_sync(0xffffffffu, sq1, o);
            #pragma unroll
            for (int k = 0; k < NK; ++k) {
                d0[k] += __shfl_xor_sync(0xffffffffu, d0[k], o);
                d1[k] += __shfl_xor_sync(0xffffffffu, d1[k], o);
            }
        }
        osq[mf][0] = sq0; osq[mf][1] = sq1;
        #pragma unroll
        for (int k = 0; k < NK; ++k) { od[mf][0][k] = d0[k]; od[mf][1][k] = d1[k]; }
    }
    __syncthreads();           // mainloop smem reads done -> red_s overlay safe

    if ((lane & 3) == 0) {
        #pragma unroll
        for (int mf = 0; mf < 2; ++mf) {
            int R0 = wm * 32 + mf * 16 + qr;
            #pragma unroll
            for (int k = 0; k < NK; ++k) {
                red_s[(wn * 128 + R0) * 9 + k]     = od[mf][0][k];
                red_s[(wn * 128 + R0 + 8) * 9 + k] = od[mf][1][k];
            }
            red_s[(wn * 128 + R0) * 9 + 8]     = osq[mf][0];
            red_s[(wn * 128 + R0 + 8) * 9 + 8] = osq[mf][1];
        }
    }
    __syncthreads();

    for (int idx = tid; idx < 128 * 9; idx += 512) {
        int row = idx / 9, kk = idx - row * 9;
        float s = red_s[(0 * 128 + row) * 9 + kk] + red_s[(1 * 128 + row) * 9 + kk]
                + red_s[(2 * 128 + row) * 9 + kk] + red_s[(3 * 128 + row) * 9 + kk];
        g_part[((size_t)(lvl * 2 + half) * NB + bm + row) * 9 + kk] = s;
    }
}

// ==== L4: combine halves, normalize, softmax over L=4 ========================
__global__ void k_final(float* __restrict__ out) {
    int id = blockIdx.x * blockDim.x + threadIdx.x;
    if (id >= NB * NK) return;
    int b = id >> 3, k = id & 7;
    float lg[NL];
    #pragma unroll
    for (int lvl = 0; lvl < NL; ++lvl) {
        const float* p0 = &g_part[((size_t)(lvl * 2 + 0) * NB + b) * 9];
        const float* p1 = &g_part[((size_t)(lvl * 2 + 1) * NB + b) * 9];
        float dq = p0[k] + p1[k];
        float sq = p0[8] + p1[8];
        lg[lvl] = dq / fmaxf(sqrtf(sq), 1e-12f);
    }
    float mx = fmaxf(fmaxf(lg[0], lg[1]), fmaxf(lg[2], lg[3]));
    float e0 = expf(lg[0] - mx), e1 = expf(lg[1] - mx);
    float e2 = expf(lg[2] - mx), e3 = expf(lg[3] - mx);
    float inv = 1.0f / (e0 + e1 + e2 + e3);
    ((float4*)out)[(size_t)b * NK + k] = make_float4(e0 * inv, e1 * inv, e2 * inv, e3 * inv);
}

extern "C" void kernel_launch(void* const* d_in, const int* in_sizes, int n_in,
                              void* d_out, int out_size) {
    PtrSet ps;
    bool interleaved = (in_sizes[1] == NP * 256);
    if (interleaved) {
        for (int i = 0; i < NL; ++i) {
            ps.pooled[i] = (const float*)d_in[6 * i + 0];
            ps.proto[i]  = (const float*)d_in[6 * i + 1];
            ps.lng[i]    = (const float*)d_in[6 * i + 2];
            ps.lnb[i]    = (const float*)d_in[6 * i + 3];
            ps.W[i]      = (const float*)d_in[6 * i + 4];
            ps.blin[i]   = (const float*)d_in[6 * i + 5];
        }
    } else {
        for (int i = 0; i < NL; ++i) {
            ps.pooled[i] = (const float*)d_in[0 + i];
            ps.proto[i]  = (const float*)d_in[4 + i];
            ps.lng[i]    = (const float*)d_in[8 + i];
            ps.lnb[i]    = (const float*)d_in[12 + i];
            ps.W[i]      = (const float*)d_in[16 + i];
            ps.blin[i]   = (const float*)d_in[20 + i];
        }
    }
    ps.text  = (const float*)d_in[24];
    ps.scale = (const float*)d_in[25];
    float* out = (float*)d_out;

    static bool attr_done = false;
    if (!attr_done) {
        cudaFuncSetAttribute(k_fused, cudaFuncAttributeMaxDynamicSharedMemorySize, SM_TOT);
        attr_done = true;
    }

    k_prep0<<<P0_WG, 256>>>(ps);                        // 0
    k_uvw<<<dim3(64, NL), ND>>>(ps);                    // 1
    k_uvw_fin<<<NL, ND>>>(ps);                          // 2
    k_fused<<<dim3(64, 2, NL), 512, SM_TOT>>>();        // 3 (ncu target)
    k_final<<<(NB * NK + 255) / 256, 256>>>(out);       // 4
}

// round 15
// speedup vs baseline: 1.2886x; 1.0384x over previous
#include <cuda_runtime.h>
#include <cuda_bf16.h>
#include <cstdint>
#include <math.h>

#define NB 8192
#define NP 64
#define NK 8
#define ND 512
#define NL 4
#define LN_EPS 1e-5f

__constant__ int c_C[NL]   = {256, 512, 1024, 2048};
__constant__ int c_off[NL] = {0, 256, 768, 1792};

// ---- scratch ----
__device__ float g_spp[NL * 8 * 2];
__device__ float g_spqp[NL * 2];
__device__ float g_u[NL * ND];
__device__ float g_v[NL * ND];
__device__ float g_w[NL * ND];
__device__ float g_up[NL * 64 * ND];
__device__ float g_vp[NL * 64 * ND];
__device__ float g_wp[NL * 64 * ND];
__device__ float g_text[NK * ND];
__device__ __nv_bfloat16 g_Wgb[3840 * ND];          // g_top ⊙ W_top (bf16, stacked)
__device__ __nv_bfloat16 g_Abf[(size_t)NB * 3840];  // pooled bf16, stacked
__device__ float g_rs[NL * NB * 2];
__device__ float g_part[(size_t)NL * 2 * NB * 9];

struct PtrSet {
    const float* pooled[NL];
    const float* proto[NL];
    const float* lng[NL];
    const float* lnb[NL];
    const float* W[NL];
    const float* blin[NL];
    const float* text;
    const float* scale;
};

// ==== L0: mega-prep: rowstats | proto spqp | text | uvw partials | Wg ========
#define P0_RS 4096
#define P0_PM 4128
#define P0_TX 4136
#define P0_UV 4392    // + 256 uvw-partial blocks (self-contained pm)
#define P0_WG 12072   // + 7680 blocks for Wg

__global__ void __launch_bounds__(256) k_prep0(PtrSet ps) {
    int blk = blockIdx.x;
    if (blk < P0_RS) {
        // ---- rowstats + bf16 convert ----
        int gw = (blk * 256 + threadIdx.x) >> 5;
        int lane = threadIdx.x & 31;
        int lvl = gw >> 13;
        int r = gw & (NB - 1);
        int C = c_C[lvl];
        const float4* __restrict__ row = (const float4*)(ps.pooled[lvl] + (size_t)r * C);
        __nv_bfloat162* __restrict__ arow =
            (__nv_bfloat162*)(g_Abf + (size_t)NB * c_off[lvl] + (size_t)r * C);
        int n4 = C >> 2;
        float S = 0.f, Q = 0.f;
        for (int j = lane; j < n4; j += 32) {
            float4 v = row[j];
            S += v.x + v.y + v.z + v.w;
            Q += v.x * v.x + v.y * v.y + v.z * v.z + v.w * v.w;
            arow[j * 2]     = __floats2bfloat162_rn(v.x, v.y);
            arow[j * 2 + 1] = __floats2bfloat162_rn(v.z, v.w);
        }
        #pragma unroll
        for (int o = 16; o; o >>= 1) {
            S += __shfl_xor_sync(0xffffffffu, S, o);
            Q += __shfl_xor_sync(0xffffffffu, Q, o);
        }
        if (lane == 0) { g_rs[gw * 2] = S; g_rs[gw * 2 + 1] = Q; }
    } else if (blk < P0_PM) {
        // ---- proto-mean spqp partials ----
        int q = blk - P0_RS;
        int lvl = q >> 3, bx = q & 7;
        int C = c_C[lvl];
        int seg = C / 8;
        int j0 = bx * seg;
        const float* __restrict__ proto = ps.proto[lvl];
        float sS = 0.f, sQ = 0.f;
        for (int j = j0 + threadIdx.x; j < j0 + seg; j += 256) {
            float s = 0.f;
            #pragma unroll 8
            for (int p = 0; p < NP; ++p) s += proto[p * C + j];
            float m = s * (1.0f / NP);
            sS += m; sQ += m * m;
        }
        __shared__ float r1[256], r2[256];
        int t = threadIdx.x;
        r1[t] = sS; r2[t] = sQ;
        __syncthreads();
        for (int o = 128; o > 0; o >>= 1) {
            if (t < o) { r1[t] += r1[t + o]; r2[t] += r2[t + o]; }
            __syncthreads();
        }
        if (t == 0) { g_spp[q * 2] = r1[0]; g_spp[q * 2 + 1] = r2[0]; }
    } else if (blk < P0_TX) {
        // ---- text normalize ----
        int k = blk - P0_PM;
        int d = threadIdx.x;
        float x0 = ps.text[k * ND + d];
        float x1 = ps.text[k * ND + 256 + d];
        __shared__ float red[256];
        red[d] = x0 * x0 + x1 * x1;
        __syncthreads();
        for (int o = 128; o > 0; o >>= 1) {
            if (d < o) red[d] += red[d + o];
            __syncthreads();
        }
        float n = fmaxf(sqrtf(red[0]), 1e-12f);
        float sc = fmaxf(ps.scale[0], 1e-4f) * (1.0f / sqrtf((float)ND));
        g_text[k * ND + d]       = x0 / n * sc;
        g_text[k * ND + 256 + d] = x1 / n * sc;
    } else if (blk < P0_UV) {
        // ---- u,v,w partials; self-contained pm slice (<=64 cols) ----
        int q = blk - P0_TX;                 // 0..255
        int lvl = q >> 6, bx = q & 63;
        int C = c_C[lvl];
        int seg = (2 * C) / 64;              // 8..64
        int j0 = bx * seg;
        const float* __restrict__ proto = ps.proto[lvl];
        const float* __restrict__ W  = ps.W[lvl];
        const float* __restrict__ gg = ps.lng[lvl];
        const float* __restrict__ bb = ps.lnb[lvl];

        __shared__ float pm_s[64];
        int pmStart = (j0 > C) ? j0 : C;     // first j needing pm
        int nPm = j0 + seg - pmStart;        // may be <= 0
        if ((int)threadIdx.x < nPm) {
            int colc = pmStart - C + threadIdx.x;
            float s = 0.f;
            #pragma unroll 8
            for (int p = 0; p < NP; ++p) s += proto[p * C + colc];
            pm_s[threadIdx.x] = s * (1.0f / NP);
        }
        __syncthreads();

        int d = threadIdx.x;                 // handles d and d+256
        float u0 = 0.f, v0 = 0.f, w0 = 0.f;
        float u1 = 0.f, v1 = 0.f, w1 = 0.f;
        #pragma unroll 4
        for (int j = j0; j < j0 + seg; ++j) {
            float gv = gg[j], bv = bb[j];
            float Wv0 = W[(size_t)j * ND + d];
            float Wv1 = W[(size_t)j * ND + d + 256];
            v0 += gv * Wv0; w0 += bv * Wv0;
            v1 += gv * Wv1; w1 += bv * Wv1;
            if (j >= pmStart) {
                float pmv = pm_s[j - pmStart] * gv;
                u0 += pmv * Wv0; u1 += pmv * Wv1;
            }
        }
        int o = (lvl * 64 + bx) * ND;
        g_up[o + d] = u0;       g_vp[o + d] = v0;       g_wp[o + d] = w0;
        g_up[o + d + 256] = u1; g_vp[o + d + 256] = v1; g_wp[o + d + 256] = w1;
    } else {
        // ---- Wg = g_top ⊙ W_top (bf16) ----
        int idx = (blk - P0_UV) * 256 + threadIdx.x;
        if (idx >= 3840 * ND) return;
        int row = idx / ND, d = idx % ND;
        int lvl, j;
        if (row < 256)       { lvl = 0; j = row; }
        else if (row < 768)  { lvl = 1; j = row - 256; }
        else if (row < 1792) { lvl = 2; j = row - 768; }
        else                 { lvl = 3; j = row - 1792; }
        g_Wgb[idx] = __float2bfloat16(ps.lng[lvl][j] * ps.W[lvl][(size_t)j * ND + d]);
    }
}

// ==== L1: reduce partials + bias + combine spqp ==============================
__global__ void k_uvw_fin(PtrSet ps) {
    int lvl = blockIdx.x, d = threadIdx.x;
    float u = 0.f, v = 0.f, w = 0.f;
    #pragma unroll 8
    for (int p = 0; p < 64; ++p) {
        int o = (lvl * 64 + p) * ND + d;
        u += g_up[o]; v += g_vp[o]; w += g_wp[o];
    }
    g_u[lvl * ND + d] = u;
    g_v[lvl * ND + d] = v;
    g_w[lvl * ND + d] = w + ps.blin[lvl][d];
    if (d == 0) {
        float s = 0.f, q = 0.f;
        #pragma unroll
        for (int p = 0; p < 8; ++p) {
            s += g_spp[(lvl * 8 + p) * 2];
            q += g_spp[(lvl * 8 + p) * 2 + 1];
        }
        g_spqp[lvl * 2] = s; g_spqp[lvl * 2 + 1] = q;
    }
}

// ===== L2: fused GEMM (bf16 mma.sync) + LN/ReLU + partial l2norm/dots ========
// BM=128, BN=256 (half of D), BK=64 stages. 512 threads = 16 warps (4x4).
// Warp tile 32x64. 3-stage cp.async pipeline, ONE sync/iter, register
// double-buffered fragments.  [R11/R14 proven — unchanged]
#define SM_AS   101376
#define SM_TEXT 156672
#define SM_UVW  164864
#define SM_TOT  167936
#define ASTRIDE 72
#define BSTRIDE 264
#define BNH 256
#define A_STAGE (128 * ASTRIDE * 2)
#define B_STAGE (64 * BSTRIDE * 2)

__device__ __forceinline__ void cp16(uint32_t dst, const void* src) {
    asm volatile("cp.async.cg.shared.global [%0], [%1], 16;\n" :: "r"(dst), "l"(src));
}

#define LOAD_FRAGS(ks, pb)                                                        \
    do {                                                                          \
        _Pragma("unroll")                                                         \
        for (int mf = 0; mf < 2; ++mf) {                                          \
            uint32_t addr = Ab + ((wm * 32 + mf * 16 + (lane & 15)) * ASTRIDE     \
                                  + (ks) + (lane >> 4) * 8) * 2;                  \
            asm volatile("ldmatrix.sync.aligned.m8n8.x4.shared.b16 "              \
                         "{%0,%1,%2,%3}, [%4];\n"                                 \
                         : "=r"(af[pb][mf][0]), "=r"(af[pb][mf][1]),              \
                           "=r"(af[pb][mf][2]), "=r"(af[pb][mf][3])               \
                         : "r"(addr));                                            \
        }                                                                         \
        _Pragma("unroll")                                                         \
        for (int p = 0; p < 4; ++p) {                                             \
            uint32_t addr = Bb + (((ks) + (lane & 15)) * BSTRIDE                  \
                                  + wn * 64 + p * 16 + (lane >> 4) * 8) * 2;      \
            asm volatile("ldmatrix.sync.aligned.m8n8.x4.trans.shared.b16 "        \
                         "{%0,%1,%2,%3}, [%4];\n"                                 \
                         : "=r"(bfr[pb][2 * p][0]), "=r"(bfr[pb][2 * p][1]),      \
                           "=r"(bfr[pb][2 * p + 1][0]),                           \
                           "=r"(bfr[pb][2 * p + 1][1])                            \
                         : "r"(addr));                                            \
        }                                                                         \
    } while (0)

__global__ void __launch_bounds__(512, 1) k_fused() {
    extern __shared__ char smem[];
    const int lvl = 3 - blockIdx.z;      // heavy levels first
    const int half = blockIdx.y;
    const int C = c_C[lvl];
    const int bm = blockIdx.x * 128;
    const int tid = threadIdx.x;
    const int wid = tid >> 5, lane = tid & 31;
    const int wm = wid >> 2, wn = wid & 3;

    const __nv_bfloat16* __restrict__ Ag = g_Abf + (size_t)NB * c_off[lvl] + (size_t)bm * C;
    const __nv_bfloat16* __restrict__ Bg = g_Wgb + (size_t)c_off[lvl] * ND + half * BNH;

    float* text_s = (float*)(smem + SM_TEXT);
    float* uvw_s  = (float*)(smem + SM_UVW);
    float* red_s  = (float*)smem;

    const uint32_t Bs_u = (uint32_t)__cvta_generic_to_shared(smem);
    const uint32_t As_u = (uint32_t)__cvta_generic_to_shared(smem + SM_AS);

    for (int i = tid; i < NK * BNH; i += 512) {
        int k = i >> 8, c = i & (BNH - 1);
        text_s[i] = g_text[k * ND + half * BNH + c];
    }
    if (tid < BNH) {
        uvw_s[tid]           = g_u[lvl * ND + half * BNH + tid];
        uvw_s[BNH + tid]     = g_v[lvl * ND + half * BNH + tid];
        uvw_s[2 * BNH + tid] = g_w[lvl * ND + half * BNH + tid];
    }

    float acc[2][8][4];
    #pragma unroll
    for (int i = 0; i < 2; ++i)
        #pragma unroll
        for (int j = 0; j < 8; ++j)
            #pragma unroll
            for (int r = 0; r < 4; ++r) acc[i][j][r] = 0.f;

    const int niter = C >> 6;            // BK=64

    auto load_stage = [&](int it) {
        int buf = it - (it / 3) * 3;
        int k0 = it << 6;
        #pragma unroll
        for (int i = 0; i < 2; ++i) {
            int idx = tid + i * 512;
            int r = idx >> 3, c = idx & 7;
            cp16(As_u + buf * A_STAGE + (r * ASTRIDE + c * 8) * 2,
                 Ag + (size_t)r * C + k0 + c * 8);
        }
        #pragma unroll
        for (int i = 0; i < 4; ++i) {
            int idx = tid + i * 512;
            int r = idx >> 5, c = idx & 31;
            cp16(Bs_u + buf * B_STAGE + (r * BSTRIDE + c * 8) * 2,
                 Bg + (size_t)(k0 + r) * ND + c * 8);
        }
        asm volatile("cp.async.commit_group;\n" ::: "memory");
    };

    load_stage(0);
    if (niter > 1) load_stage(1);

    for (int it = 0; it < niter; ++it) {
        if (it + 1 < niter)
            asm volatile("cp.async.wait_group 1;\n" ::: "memory");
        else
            asm volatile("cp.async.wait_group 0;\n" ::: "memory");
        __syncthreads();
        if (it + 2 < niter) load_stage(it + 2);

        const int buf = it - (it / 3) * 3;
        const uint32_t Ab = As_u + buf * A_STAGE;
        const uint32_t Bb = Bs_u + buf * B_STAGE;

        uint32_t af[2][2][4];
        uint32_t bfr[2][8][2];
        LOAD_FRAGS(0, 0);

        #pragma unroll
        for (int ks4 = 0; ks4 < 4; ++ks4) {
            const int cur = ks4 & 1;
            if (ks4 < 3) {
                const int nxt = cur ^ 1;
                LOAD_FRAGS((ks4 + 1) * 16, nxt);
            }
            #pragma unroll
            for (int mf = 0; mf < 2; ++mf)
                #pragma unroll
                for (int nf = 0; nf < 8; ++nf)
                    asm volatile(
                        "mma.sync.aligned.m16n8k16.row.col.f32.bf16.bf16.f32 "
                        "{%0,%1,%2,%3}, {%4,%5,%6,%7}, {%8,%9}, {%0,%1,%2,%3};\n"
                        : "+f"(acc[mf][nf][0]), "+f"(acc[mf][nf][1]),
                          "+f"(acc[mf][nf][2]), "+f"(acc[mf][nf][3])
                        : "r"(af[cur][mf][0]), "r"(af[cur][mf][1]),
                          "r"(af[cur][mf][2]), "r"(af[cur][mf][3]),
                          "r"(bfr[cur][nf][0]), "r"(bfr[cur][nf][1]));
        }
    }

    // ---- epilogue: LN + ReLU, partial sq + 8 text dots per row ----
    const float Sp = g_spqp[lvl * 2], Qp = g_spqp[lvl * 2 + 1];
    const float inv2C = 1.0f / (2.0f * (float)C);
    const int qr = lane >> 2, qc = (lane & 3) * 2;

    float osq[2][2];
    float od[2][2][NK];
    #pragma unroll
    for (int mf = 0; mf < 2; ++mf) {
        int R0 = wm * 32 + mf * 16 + qr;
        float2 sqr0 = ((const float2*)g_rs)[lvl * NB + bm + R0];
        float2 sqr1 = ((const float2*)g_rs)[lvl * NB + bm + R0 + 8];
        float mean0 = (sqr0.x + Sp) * inv2C;
        float var0  = (sqr0.y + Qp) * inv2C - mean0 * mean0;
        float s0 = rsqrtf(var0 + LN_EPS), sm0 = s0 * mean0;
        float mean1 = (sqr1.x + Sp) * inv2C;
        float var1  = (sqr1.y + Qp) * inv2C - mean1 * mean1;
        float s1 = rsqrtf(var1 + LN_EPS), sm1 = s1 * mean1;

        float sq0 = 0.f, sq1 = 0.f;
        float d0[NK], d1[NK];
        #pragma unroll
        for (int k = 0; k < NK; ++k) { d0[k] = 0.f; d1[k] = 0.f; }

        #pragma unroll
        for (int nf = 0; nf < 8; ++nf) {
            #pragma unroll
            for (int r = 0; r < 4; ++r) {
                int col = wn * 64 + nf * 8 + qc + (r & 1);
                float s  = (r < 2) ? s0  : s1;
                float sm = (r < 2) ? sm0 : sm1;
                float hv = s * (acc[mf][nf][r] + uvw_s[col]) - sm * uvw_s[BNH + col]
                           + uvw_s[2 * BNH + col];
                hv = fmaxf(hv, 0.f);
                if (r < 2) {
                    sq0 += hv * hv;
                    #pragma unroll
                    for (int k = 0; k < NK; ++k) d0[k] += hv * text_s[k * BNH + col];
                } else {
                    sq1 += hv * hv;
                    #pragma unroll
                    for (int k = 0; k < NK; ++k) d1[k] += hv * text_s[k * BNH + col];
                }
            }
        }
        #pragma unroll
        for (int o = 1; o <= 2; o <<= 1) {
            sq0 += __shfl_xor_sync(0xffffffffu, sq0, o);
            sq1 += __shfl_xor_sync(0xffffffffu, sq1, o);
            #pragma unroll
            for (int k = 0; k < NK; ++k) {
                d0[k] += __shfl_xor_sync(0xffffffffu, d0[k], o);
                d1[k] += __shfl_xor_sync(0xffffffffu, d1[k], o);
            }
        }
        osq[mf][0] = sq0; osq[mf][1] = sq1;
        #pragma unroll
        for (int k = 0; k < NK; ++k) { od[mf][0][k] = d0[k]; od[mf][1][k] = d1[k]; }
    }
    __syncthreads();           // mainloop smem reads done -> red_s overlay safe

    if ((lane & 3) == 0) {
        #pragma unroll
        for (int mf = 0; mf < 2; ++mf) {
            int R0 = wm * 32 + mf * 16 + qr;
            #pragma unroll
            for (int k = 0; k < NK; ++k) {
                red_s[(wn * 128 + R0) * 9 + k]     = od[mf][0][k];
                red_s[(wn * 128 + R0 + 8) * 9 + k] = od[mf][1][k];
            }
            red_s[(wn * 128 + R0) * 9 + 8]     = osq[mf][0];
            red_s[(wn * 128 + R0 + 8) * 9 + 8] = osq[mf][1];
        }
    }
    __syncthreads();

    for (int idx = tid; idx < 128 * 9; idx += 512) {
        int row = idx / 9, kk = idx - row * 9;
        float s = red_s[(0 * 128 + row) * 9 + kk] + red_s[(1 * 128 + row) * 9 + kk]
                + red_s[(2 * 128 + row) * 9 + kk] + red_s[(3 * 128 + row) * 9 + kk];
        g_part[((size_t)(lvl * 2 + half) * NB + bm + row) * 9 + kk] = s;
    }
}

// ==== L3: combine halves, normalize, softmax over L=4 ========================
__global__ void k_final(float* __restrict__ out) {
    int id = blockIdx.x * blockDim.x + threadIdx.x;
    if (id >= NB * NK) return;
    int b = id >> 3, k = id & 7;
    float lg[NL];
    #pragma unroll
    for (int lvl = 0; lvl < NL; ++lvl) {
        const float* p0 = &g_part[((size_t)(lvl * 2 + 0) * NB + b) * 9];
        const float* p1 = &g_part[((size_t)(lvl * 2 + 1) * NB + b) * 9];
        float dq = p0[k] + p1[k];
        float sq = p0[8] + p1[8];
        lg[lvl] = dq / fmaxf(sqrtf(sq), 1e-12f);
    }
    float mx = fmaxf(fmaxf(lg[0], lg[1]), fmaxf(lg[2], lg[3]));
    float e0 = expf(lg[0] - mx), e1 = expf(lg[1] - mx);
    float e2 = expf(lg[2] - mx), e3 = expf(lg[3] - mx);
    float inv = 1.0f / (e0 + e1 + e2 + e3);
    ((float4*)out)[(size_t)b * NK + k] = make_float4(e0 * inv, e1 * inv, e2 * inv, e3 * inv);
}

extern "C" void kernel_launch(void* const* d_in, const int* in_sizes, int n_in,
                              void* d_out, int out_size) {
    PtrSet ps;
    bool interleaved = (in_sizes[1] == NP * 256);
    if (interleaved) {
        for (int i = 0; i < NL; ++i) {
            ps.pooled[i] = (const float*)d_in[6 * i + 0];
            ps.proto[i]  = (const float*)d_in[6 * i + 1];
            ps.lng[i]    = (const float*)d_in[6 * i + 2];
            ps.lnb[i]    = (const float*)d_in[6 * i + 3];
            ps.W[i]      = (const float*)d_in[6 * i + 4];
            ps.blin[i]   = (const float*)d_in[6 * i + 5];
        }
    } else {
        for (int i = 0; i < NL; ++i) {
            ps.pooled[i] = (const float*)d_in[0 + i];
            ps.proto[i]  = (const float*)d_in[4 + i];
            ps.lng[i]    = (const float*)d_in[8 + i];
            ps.lnb[i]    = (const float*)d_in[12 + i];
            ps.W[i]      = (const float*)d_in[16 + i];
            ps.blin[i]   = (const float*)d_in[20 + i];
        }
    }
    ps.text  = (const float*)d_in[24];
    ps.scale = (const float*)d_in[25];
    float* out = (float*)d_out;

    static bool attr_done = false;
    if (!attr_done) {
        cudaFuncSetAttribute(k_fused, cudaFuncAttributeMaxDynamicSharedMemorySize, SM_TOT);
        attr_done = true;
    }

    k_prep0<<<P0_WG, 256>>>(ps);                        // 0
    k_uvw_fin<<<NL, ND>>>(ps);                          // 1
    k_fused<<<dim3(64, 2, NL), 512, SM_TOT>>>();        // 2 (ncu target shifts; acceptable)
    k_final<<<(NB * NK + 255) / 256, 256>>>(out);       // 3
}